// round 9
// baseline (speedup 1.0000x reference)
#include <cuda_runtime.h>
#include <cstdint>

// Haar 3D, stride-2, 2x2x2 depthwise, 8 filters per channel.
// x: [N=2, C=16, D=128, H=128, W=128] fp32
// y: [N=2, C*8=128, D2=64, H2=64, W2=64] fp32
//
// SINGLE-WAVE PERSISTENT kernel: grid = 512 CTAs (<= 592 = 4 CTAs/SM x 148),
// each CTA processes exactly 4 (n,c,d2) slabs: ncd = bid + j*512, j=0..3.
// Eliminates the 3.46-wave quantization of the 2048-CTA launch (each wave
// boundary drains the DRAM request queues; tail waves underfill the chip).
//
// The prefetch-distance-2 pipeline is FLAT across slab boundaries: iteration
// m = 0..31 (slab j = m>>3, row k = m&7), and iteration m+2's 4 float4 loads
// are issued before iteration m's butterfly + 8 float2 stores. The load queue
// drains exactly once, at kernel end.

#define C_IN   16
#define D_IN   128
#define H_IN   128
#define W_IN   128
#define D2     64
#define H2     64
#define W2     64
#define GRID   512
#define ITERS  32          // 4 slabs x 8 rows per slab

struct Quad { float4 a00, a01, a10, a11; };

__device__ __forceinline__ Quad load_quad(const float* __restrict__ xin)
{
    Quad q;
    q.a00 = __ldcs(reinterpret_cast<const float4*>(xin));
    q.a01 = __ldcs(reinterpret_cast<const float4*>(xin + W_IN));
    q.a10 = __ldcs(reinterpret_cast<const float4*>(xin + H_IN * W_IN));
    q.a11 = __ldcs(reinterpret_cast<const float4*>(xin + H_IN * W_IN + W_IN));
    return q;
}

__global__ __launch_bounds__(256, 4) void haar3d_kernel(
    const float* __restrict__ x, float* __restrict__ y)
{
    const int w4  = threadIdx.x;        // 0..31: 2 w-blocks (4 floats)
    const int ty  = threadIdx.y;        // 0..7
    const int bid = blockIdx.x;         // 0..511

    const size_t plane = (size_t)D2 * H2 * W2;   // 262144

    // Input row pointer for flat iteration m (slab j = m>>3, row k = m&7)
    auto in_ptr = [&](int m) -> const float* {
        const int j   = m >> 3;
        const int k   = m & 7;
        const int ncd = bid + (j << 9);          // bid + j*512, < 2048
        const int d2  = ncd & 63;
        const int nc  = ncd >> 6;
        return x + ((size_t)nc * D_IN + 2 * d2) * (size_t)(H_IN * W_IN)
                 + (size_t)(2 * (ty + 8 * k)) * W_IN
                 + 4 * w4;
    };

    // Prologue: fill pipeline
    Quad b0 = load_quad(in_ptr(0));
    Quad b1 = load_quad(in_ptr(1));

    #pragma unroll 4
    for (int m = 0; m < ITERS; m++) {
        // Prefetch m+2 before consuming b0
        Quad b2;
        if (m < ITERS - 2) b2 = load_quad(in_ptr(m + 2));

        const float4 c00 = b0.a00, c01 = b0.a01, c10 = b0.a10, c11 = b0.a11;

        // ---- Block 0 (w pair .x,.y) ----
        float t0_00 = c00.x + c00.y, t1_00 = c00.x - c00.y;
        float t0_01 = c01.x + c01.y, t1_01 = c01.x - c01.y;
        float t0_10 = c10.x + c10.y, t1_10 = c10.x - c10.y;
        float t0_11 = c11.x + c11.y, t1_11 = c11.x - c11.y;
        float u00_0 = t0_00 + t0_01, u10_0 = t0_00 - t0_01;
        float u01_0 = t1_00 + t1_01, u11_0 = t1_00 - t1_01;
        float u00_1 = t0_10 + t0_11, u10_1 = t0_10 - t0_11;
        float u01_1 = t1_10 + t1_11, u11_1 = t1_10 - t1_11;
        float o0_b0 = (u00_0 + u00_1) * 0.125f;
        float o1_b0 = (u01_0 + u01_1) * 0.125f;
        float o2_b0 = (u10_0 + u10_1) * 0.125f;
        float o3_b0 = (u11_0 + u11_1) * 0.125f;
        float o4_b0 = (u00_0 - u00_1) * 0.125f;
        float o5_b0 = (u01_0 - u01_1) * 0.125f;
        float o6_b0 = (u10_0 - u10_1) * 0.125f;
        float o7_b0 = (u11_0 - u11_1) * 0.125f;

        // ---- Block 1 (w pair .z,.w) ----
        t0_00 = c00.z + c00.w; t1_00 = c00.z - c00.w;
        t0_01 = c01.z + c01.w; t1_01 = c01.z - c01.w;
        t0_10 = c10.z + c10.w; t1_10 = c10.z - c10.w;
        t0_11 = c11.z + c11.w; t1_11 = c11.z - c11.w;
        u00_0 = t0_00 + t0_01; u10_0 = t0_00 - t0_01;
        u01_0 = t1_00 + t1_01; u11_0 = t1_00 - t1_01;
        u00_1 = t0_10 + t0_11; u10_1 = t0_10 - t0_11;
        u01_1 = t1_10 + t1_11; u11_1 = t1_10 - t1_11;
        float o0_b1 = (u00_0 + u00_1) * 0.125f;
        float o1_b1 = (u01_0 + u01_1) * 0.125f;
        float o2_b1 = (u10_0 + u10_1) * 0.125f;
        float o3_b1 = (u11_0 + u11_1) * 0.125f;
        float o4_b1 = (u00_0 - u00_1) * 0.125f;
        float o5_b1 = (u01_0 - u01_1) * 0.125f;
        float o6_b1 = (u10_0 - u10_1) * 0.125f;
        float o7_b1 = (u11_0 - u11_1) * 0.125f;

        // Output pointer for iteration m
        {
            const int j   = m >> 3;
            const int k   = m & 7;
            const int ncd = bid + (j << 9);
            const int d2  = ncd & 63;
            const int nc  = ncd >> 6;
            float* yo = y + (size_t)nc * 8 * plane
                          + (size_t)d2 * (H2 * W2)
                          + (size_t)(ty + 8 * k) * W2
                          + 2 * w4;
            __stcs(reinterpret_cast<float2*>(yo + 0 * plane), make_float2(o0_b0, o0_b1));
            __stcs(reinterpret_cast<float2*>(yo + 1 * plane), make_float2(o1_b0, o1_b1));
            __stcs(reinterpret_cast<float2*>(yo + 2 * plane), make_float2(o2_b0, o2_b1));
            __stcs(reinterpret_cast<float2*>(yo + 3 * plane), make_float2(o3_b0, o3_b1));
            __stcs(reinterpret_cast<float2*>(yo + 4 * plane), make_float2(o4_b0, o4_b1));
            __stcs(reinterpret_cast<float2*>(yo + 5 * plane), make_float2(o5_b0, o5_b1));
            __stcs(reinterpret_cast<float2*>(yo + 6 * plane), make_float2(o6_b0, o6_b1));
            __stcs(reinterpret_cast<float2*>(yo + 7 * plane), make_float2(o7_b0, o7_b1));
        }

        // Rotate pipeline
        b0 = b1;
        b1 = b2;
    }
}

extern "C" void kernel_launch(void* const* d_in, const int* in_sizes, int n_in,
                              void* d_out, int out_size)
{
    const float* x = (const float*)d_in[0];
    // d_in[1] is the fixed Haar filter bank; its values (+-0.125 products) are
    // hardcoded in the butterfly above.
    float* y = (float*)d_out;

    // Single wave: 512 CTAs, each owns 4 (n,c,d2) slabs.
    dim3 block(32, 8, 1);
    dim3 grid(GRID, 1, 1);
    haar3d_kernel<<<grid, block>>>(x, y);
}

// round 10
// speedup vs baseline: 1.1041x; 1.1041x over previous
#include <cuda_runtime.h>
#include <cstdint>

// Haar 3D, stride-2, 2x2x2 depthwise, 8 filters per channel.
// x: [N=2, C=16, D=128, H=128, W=128] fp32
// y: [N=2, C*8=128, D2=64, H2=64, W2=64] fp32
//
// R7 structure (best so far): one CTA per (n,c,d2) slab, prefetch-distance-2
// register pipeline over h2 (8 outstanding LDGs/warp steady-state).
// NEW: prefetch.global.L2 of row k+4 — adds DRAM->L2 requests in flight with
// ZERO register/scoreboard cost, so the real LDG at distance 2 becomes an L2
// hit and per-warp DRAM-side queue depth ~doubles without hurting occupancy.

#define C_IN   16
#define D_IN   128
#define H_IN   128
#define W_IN   128
#define D2     64
#define H2     64
#define W2     64

struct Quad { float4 a00, a01, a10, a11; };

__device__ __forceinline__ Quad load_quad(const float* __restrict__ xin)
{
    Quad q;
    q.a00 = __ldcs(reinterpret_cast<const float4*>(xin));
    q.a01 = __ldcs(reinterpret_cast<const float4*>(xin + W_IN));
    q.a10 = __ldcs(reinterpret_cast<const float4*>(xin + H_IN * W_IN));
    q.a11 = __ldcs(reinterpret_cast<const float4*>(xin + H_IN * W_IN + W_IN));
    return q;
}

__device__ __forceinline__ void prefetch_quad_l2(const float* __restrict__ xin)
{
    asm volatile("prefetch.global.L2 [%0];" :: "l"(xin));
    asm volatile("prefetch.global.L2 [%0];" :: "l"(xin + W_IN));
    asm volatile("prefetch.global.L2 [%0];" :: "l"(xin + H_IN * W_IN));
    asm volatile("prefetch.global.L2 [%0];" :: "l"(xin + H_IN * W_IN + W_IN));
}

__global__ __launch_bounds__(256) void haar3d_kernel(
    const float* __restrict__ x, float* __restrict__ y)
{
    const int w4  = threadIdx.x;        // 0..31: 2 w-blocks (4 floats)
    const int ty  = threadIdx.y;        // 0..7
    const int ncd = blockIdx.x;         // (n*C + c)*64 + d2
    const int d2  = ncd & 63;
    const int nc  = ncd >> 6;

    const float* xin0 = x
        + ((size_t)nc * D_IN + 2 * d2) * (size_t)(H_IN * W_IN)
        + 4 * w4;

    const size_t plane = (size_t)D2 * H2 * W2;   // 262144
    float* yo0 = y + (size_t)nc * 8 * plane
                   + (size_t)d2 * (H2 * W2)
                   + 2 * w4;

    // Row address for pipeline stage k: h2 = ty + 8*k
    #define ROW_PTR(k) (xin0 + (size_t)(2 * (ty + 8 * (k))) * W_IN)

    // Prologue: fill pipeline (k=0, k=1 loads; k=2, k=3 L2 prefetches)
    Quad b0 = load_quad(ROW_PTR(0));
    Quad b1 = load_quad(ROW_PTR(1));
    prefetch_quad_l2(ROW_PTR(2));
    prefetch_quad_l2(ROW_PTR(3));

    #pragma unroll
    for (int k = 0; k < 8; k++) {
        // L2-prefetch k+4, then register-load k+2, before consuming b0.
        if (k < 4) prefetch_quad_l2(ROW_PTR(k + 4));
        Quad b2;
        if (k < 6) b2 = load_quad(ROW_PTR(k + 2));

        const float4 c00 = b0.a00, c01 = b0.a01, c10 = b0.a10, c11 = b0.a11;

        // ---- Block 0 (w pair .x,.y) ----
        float t0_00 = c00.x + c00.y, t1_00 = c00.x - c00.y;
        float t0_01 = c01.x + c01.y, t1_01 = c01.x - c01.y;
        float t0_10 = c10.x + c10.y, t1_10 = c10.x - c10.y;
        float t0_11 = c11.x + c11.y, t1_11 = c11.x - c11.y;
        float u00_0 = t0_00 + t0_01, u10_0 = t0_00 - t0_01;
        float u01_0 = t1_00 + t1_01, u11_0 = t1_00 - t1_01;
        float u00_1 = t0_10 + t0_11, u10_1 = t0_10 - t0_11;
        float u01_1 = t1_10 + t1_11, u11_1 = t1_10 - t1_11;
        float o0_b0 = (u00_0 + u00_1) * 0.125f;
        float o1_b0 = (u01_0 + u01_1) * 0.125f;
        float o2_b0 = (u10_0 + u10_1) * 0.125f;
        float o3_b0 = (u11_0 + u11_1) * 0.125f;
        float o4_b0 = (u00_0 - u00_1) * 0.125f;
        float o5_b0 = (u01_0 - u01_1) * 0.125f;
        float o6_b0 = (u10_0 - u10_1) * 0.125f;
        float o7_b0 = (u11_0 - u11_1) * 0.125f;

        // ---- Block 1 (w pair .z,.w) ----
        t0_00 = c00.z + c00.w; t1_00 = c00.z - c00.w;
        t0_01 = c01.z + c01.w; t1_01 = c01.z - c01.w;
        t0_10 = c10.z + c10.w; t1_10 = c10.z - c10.w;
        t0_11 = c11.z + c11.w; t1_11 = c11.z - c11.w;
        u00_0 = t0_00 + t0_01; u10_0 = t0_00 - t0_01;
        u01_0 = t1_00 + t1_01; u11_0 = t1_00 - t1_01;
        u00_1 = t0_10 + t0_11; u10_1 = t0_10 - t0_11;
        u01_1 = t1_10 + t1_11; u11_1 = t1_10 - t1_11;
        float o0_b1 = (u00_0 + u00_1) * 0.125f;
        float o1_b1 = (u01_0 + u01_1) * 0.125f;
        float o2_b1 = (u10_0 + u10_1) * 0.125f;
        float o3_b1 = (u11_0 + u11_1) * 0.125f;
        float o4_b1 = (u00_0 - u00_1) * 0.125f;
        float o5_b1 = (u01_0 - u01_1) * 0.125f;
        float o6_b1 = (u10_0 - u10_1) * 0.125f;
        float o7_b1 = (u11_0 - u11_1) * 0.125f;

        float* yo = yo0 + (size_t)(ty + 8 * k) * W2;
        __stcs(reinterpret_cast<float2*>(yo + 0 * plane), make_float2(o0_b0, o0_b1));
        __stcs(reinterpret_cast<float2*>(yo + 1 * plane), make_float2(o1_b0, o1_b1));
        __stcs(reinterpret_cast<float2*>(yo + 2 * plane), make_float2(o2_b0, o2_b1));
        __stcs(reinterpret_cast<float2*>(yo + 3 * plane), make_float2(o3_b0, o3_b1));
        __stcs(reinterpret_cast<float2*>(yo + 4 * plane), make_float2(o4_b0, o4_b1));
        __stcs(reinterpret_cast<float2*>(yo + 5 * plane), make_float2(o5_b0, o5_b1));
        __stcs(reinterpret_cast<float2*>(yo + 6 * plane), make_float2(o6_b0, o6_b1));
        __stcs(reinterpret_cast<float2*>(yo + 7 * plane), make_float2(o7_b0, o7_b1));

        // Rotate pipeline
        b0 = b1;
        b1 = b2;
    }
    #undef ROW_PTR
}

extern "C" void kernel_launch(void* const* d_in, const int* in_sizes, int n_in,
                              void* d_out, int out_size)
{
    const float* x = (const float*)d_in[0];
    // d_in[1] is the fixed Haar filter bank; its values (+-0.125 products) are
    // hardcoded in the butterfly above.
    float* y = (float*)d_out;

    // One CTA per (n, c, d2) slab: grid = 2*16*64 = 2048, block = 32x8.
    dim3 block(32, 8, 1);
    dim3 grid(2 * C_IN * D2, 1, 1);
    haar3d_kernel<<<grid, block>>>(x, y);
}

// round 11
// speedup vs baseline: 1.1276x; 1.0213x over previous
#include <cuda_runtime.h>
#include <cstdint>

// Haar 3D, stride-2, 2x2x2 depthwise, 8 filters per channel.
// x: [N=2, C=16, D=128, H=128, W=128] fp32
// y: [N=2, C*8=128, D2=64, H2=64, W2=64] fp32
//
// TERMINAL KERNEL (R7 structure — empirical best across 7 variants):
// one CTA per (n,c,d2) slab; prefetch-distance-2 register pipeline over h2:
// while iteration k's butterfly + 8 float2 stores execute, the 4 float4 loads
// of BOTH k+1 and k+2 are in flight (8 outstanding LDGs/warp steady-state).
// Achieves 6.31 TB/s = the B300 LTS chip-throughput cap (~6300 B/cyc,
// path-independent); traffic is compulsory (536 MB, each byte touched once),
// so this is the roofline for this problem on this chip.

#define C_IN   16
#define D_IN   128
#define H_IN   128
#define W_IN   128
#define D2     64
#define H2     64
#define W2     64

struct Quad { float4 a00, a01, a10, a11; };

__device__ __forceinline__ Quad load_quad(const float* __restrict__ xin)
{
    Quad q;
    q.a00 = __ldcs(reinterpret_cast<const float4*>(xin));
    q.a01 = __ldcs(reinterpret_cast<const float4*>(xin + W_IN));
    q.a10 = __ldcs(reinterpret_cast<const float4*>(xin + H_IN * W_IN));
    q.a11 = __ldcs(reinterpret_cast<const float4*>(xin + H_IN * W_IN + W_IN));
    return q;
}

__global__ __launch_bounds__(256) void haar3d_kernel(
    const float* __restrict__ x, float* __restrict__ y)
{
    const int w4  = threadIdx.x;        // 0..31: 2 w-blocks (4 floats)
    const int ty  = threadIdx.y;        // 0..7
    const int ncd = blockIdx.x;         // (n*C + c)*64 + d2
    const int d2  = ncd & 63;
    const int nc  = ncd >> 6;

    const float* xin0 = x
        + ((size_t)nc * D_IN + 2 * d2) * (size_t)(H_IN * W_IN)
        + 4 * w4;

    const size_t plane = (size_t)D2 * H2 * W2;   // 262144
    float* yo0 = y + (size_t)nc * 8 * plane
                   + (size_t)d2 * (H2 * W2)
                   + 2 * w4;

    // Row address for pipeline stage k: h2 = ty + 8*k  -> byte row 2*h2
    #define ROW_PTR(k) (xin0 + (size_t)(2 * (ty + 8 * (k))) * W_IN)

    // Prologue: fill pipeline (k=0, k=1 in flight)
    Quad b0 = load_quad(ROW_PTR(0));
    Quad b1 = load_quad(ROW_PTR(1));

    #pragma unroll
    for (int k = 0; k < 8; k++) {
        // Prefetch k+2 before touching b0 (its loads span two compute phases)
        Quad b2;
        if (k < 6) b2 = load_quad(ROW_PTR(k + 2));

        const float4 c00 = b0.a00, c01 = b0.a01, c10 = b0.a10, c11 = b0.a11;

        // ---- Block 0 (w pair .x,.y) ----
        float t0_00 = c00.x + c00.y, t1_00 = c00.x - c00.y;
        float t0_01 = c01.x + c01.y, t1_01 = c01.x - c01.y;
        float t0_10 = c10.x + c10.y, t1_10 = c10.x - c10.y;
        float t0_11 = c11.x + c11.y, t1_11 = c11.x - c11.y;
        float u00_0 = t0_00 + t0_01, u10_0 = t0_00 - t0_01;
        float u01_0 = t1_00 + t1_01, u11_0 = t1_00 - t1_01;
        float u00_1 = t0_10 + t0_11, u10_1 = t0_10 - t0_11;
        float u01_1 = t1_10 + t1_11, u11_1 = t1_10 - t1_11;
        float o0_b0 = (u00_0 + u00_1) * 0.125f;
        float o1_b0 = (u01_0 + u01_1) * 0.125f;
        float o2_b0 = (u10_0 + u10_1) * 0.125f;
        float o3_b0 = (u11_0 + u11_1) * 0.125f;
        float o4_b0 = (u00_0 - u00_1) * 0.125f;
        float o5_b0 = (u01_0 - u01_1) * 0.125f;
        float o6_b0 = (u10_0 - u10_1) * 0.125f;
        float o7_b0 = (u11_0 - u11_1) * 0.125f;

        // ---- Block 1 (w pair .z,.w) ----
        t0_00 = c00.z + c00.w; t1_00 = c00.z - c00.w;
        t0_01 = c01.z + c01.w; t1_01 = c01.z - c01.w;
        t0_10 = c10.z + c10.w; t1_10 = c10.z - c10.w;
        t0_11 = c11.z + c11.w; t1_11 = c11.z - c11.w;
        u00_0 = t0_00 + t0_01; u10_0 = t0_00 - t0_01;
        u01_0 = t1_00 + t1_01; u11_0 = t1_00 - t1_01;
        u00_1 = t0_10 + t0_11; u10_1 = t0_10 - t0_11;
        u01_1 = t1_10 + t1_11; u11_1 = t1_10 - t1_11;
        float o0_b1 = (u00_0 + u00_1) * 0.125f;
        float o1_b1 = (u01_0 + u01_1) * 0.125f;
        float o2_b1 = (u10_0 + u10_1) * 0.125f;
        float o3_b1 = (u11_0 + u11_1) * 0.125f;
        float o4_b1 = (u00_0 - u00_1) * 0.125f;
        float o5_b1 = (u01_0 - u01_1) * 0.125f;
        float o6_b1 = (u10_0 - u10_1) * 0.125f;
        float o7_b1 = (u11_0 - u11_1) * 0.125f;

        float* yo = yo0 + (size_t)(ty + 8 * k) * W2;
        __stcs(reinterpret_cast<float2*>(yo + 0 * plane), make_float2(o0_b0, o0_b1));
        __stcs(reinterpret_cast<float2*>(yo + 1 * plane), make_float2(o1_b0, o1_b1));
        __stcs(reinterpret_cast<float2*>(yo + 2 * plane), make_float2(o2_b0, o2_b1));
        __stcs(reinterpret_cast<float2*>(yo + 3 * plane), make_float2(o3_b0, o3_b1));
        __stcs(reinterpret_cast<float2*>(yo + 4 * plane), make_float2(o4_b0, o4_b1));
        __stcs(reinterpret_cast<float2*>(yo + 5 * plane), make_float2(o5_b0, o5_b1));
        __stcs(reinterpret_cast<float2*>(yo + 6 * plane), make_float2(o6_b0, o6_b1));
        __stcs(reinterpret_cast<float2*>(yo + 7 * plane), make_float2(o7_b0, o7_b1));

        // Rotate pipeline
        b0 = b1;
        b1 = b2;
    }
    #undef ROW_PTR
}

extern "C" void kernel_launch(void* const* d_in, const int* in_sizes, int n_in,
                              void* d_out, int out_size)
{
    const float* x = (const float*)d_in[0];
    // d_in[1] is the fixed Haar filter bank; its values (+-0.125 products) are
    // hardcoded in the butterfly above.
    float* y = (float*)d_out;

    // One CTA per (n, c, d2) slab: grid = 2*16*64 = 2048, block = 32x8.
    dim3 block(32, 8, 1);
    dim3 grid(2 * C_IN * D2, 1, 1);
    haar3d_kernel<<<grid, block>>>(x, y);
}